// round 5
// baseline (speedup 1.0000x reference)
#include <cuda_runtime.h>
#include <cuda_bf16.h>
#include <cstdint>

// ============================================================================
// x(8,4096,768) fp32 -> int8 quant -> GEMM vs weight_t(768,768) int8 (promoted
// to int32/fp32 by harness; detected) -> int32 acc * 2e-4 + bias -> fp32 out.
// Legacy mma.sync int8 path (compute_103 baseline PTX; tcgen05 unavailable).
// R5: TN=96 -> 2048 tiles, 2 CTA/SM -> 6.92 waves -> 98.8% wave efficiency
//     (was 10.38 -> 94.3%). quant_kernel gets MLP=4.
// ============================================================================
static constexpr int N_TOK = 32768;
static constexpr int KDIM  = 768;
static constexpr int MDIM  = 768;

static constexpr int TM = 128;      // token tile
static constexpr int TN = 96;       // out-col tile
static constexpr int TK = 64;       // K bytes per stage
static constexpr int STAGES = 5;
static constexpr int NSTAGE_ITERS = KDIM / TK;   // 12
static constexpr int ROWPAD = 80;   // 64B data padded to 80B: conflict-free ldmatrix
static constexpr int A_TILE_BYTES = TM * ROWPAD;        // 10240
static constexpr int B_TILE_BYTES = TN * ROWPAD;        // 7680
static constexpr int STAGE_BYTES  = A_TILE_BYTES + B_TILE_BYTES;  // 17920
static constexpr int SMEM_TOTAL   = STAGES * STAGE_BYTES;         // 89600 -> 2 CTA/SM

// Scratch (__device__ globals: the allowed allocation-free path)
__device__ int8_t g_xq[(size_t)N_TOK * KDIM];   // quantized activations [N,K]
__device__ int8_t g_wb[(size_t)MDIM * KDIM];    // weight transposed to [M,K]

// ============================================================================
// PTX helpers (baseline sm_75/sm_80 era, safe at compute_103)
// ============================================================================
__device__ __forceinline__ uint32_t smem_to_u32(const void* p) {
    uint32_t a;
    asm("{ .reg .u64 t; cvta.to.shared.u64 t, %1; cvt.u32.u64 %0, t; }" : "=r"(a) : "l"(p));
    return a;
}

__device__ __forceinline__ void cp_async16(uint32_t dst, const void* src) {
    asm volatile("cp.async.cg.shared.global [%0], [%1], 16;" :: "r"(dst), "l"(src));
}
#define CP_COMMIT() asm volatile("cp.async.commit_group;" ::: "memory")
#define CP_WAIT3()  asm volatile("cp.async.wait_group 3;" ::: "memory")

__device__ __forceinline__ void ldmatrix_x4(uint32_t* r, uint32_t addr) {
    asm volatile("ldmatrix.sync.aligned.m8n8.x4.shared.b16 {%0,%1,%2,%3}, [%4];"
                 : "=r"(r[0]), "=r"(r[1]), "=r"(r[2]), "=r"(r[3]) : "r"(addr));
}
__device__ __forceinline__ void ldmatrix_x2(uint32_t* r, uint32_t addr) {
    asm volatile("ldmatrix.sync.aligned.m8n8.x2.shared.b16 {%0,%1}, [%2];"
                 : "=r"(r[0]), "=r"(r[1]) : "r"(addr));
}

__device__ __forceinline__ void mma_s8(int* c, const uint32_t* a, const uint32_t* b) {
    asm volatile(
        "mma.sync.aligned.m16n8k32.row.col.s32.s8.s8.s32 "
        "{%0,%1,%2,%3}, {%4,%5,%6,%7}, {%8,%9}, {%0,%1,%2,%3};"
        : "+r"(c[0]), "+r"(c[1]), "+r"(c[2]), "+r"(c[3])
        : "r"(a[0]), "r"(a[1]), "r"(a[2]), "r"(a[3]), "r"(b[0]), "r"(b[1]));
}

// ============================================================================
// Kernel 1: quantize x -> int8. q = clamp(round(x / 0.02f), -128, 127),
// IEEE fp32 division to mirror the reference. 4 float4 per thread (MLP=4).
// ============================================================================
__global__ __launch_bounds__(256) void quant_kernel(const float* __restrict__ x) {
    const int base = blockIdx.x * 1024 + threadIdx.x;   // float4 index
    const float4* xv = reinterpret_cast<const float4*>(x);
    float4 v[4];
#pragma unroll
    for (int k = 0; k < 4; ++k) v[k] = xv[base + k * 256];
#pragma unroll
    for (int k = 0; k < 4; ++k) {
        float r0 = fminf(fmaxf(rintf(__fdiv_rn(v[k].x, 0.02f)), -128.f), 127.f);
        float r1 = fminf(fmaxf(rintf(__fdiv_rn(v[k].y, 0.02f)), -128.f), 127.f);
        float r2 = fminf(fmaxf(rintf(__fdiv_rn(v[k].z, 0.02f)), -128.f), 127.f);
        float r3 = fminf(fmaxf(rintf(__fdiv_rn(v[k].w, 0.02f)), -128.f), 127.f);
        int q0 = (int)r0, q1 = (int)r1, q2 = (int)r2, q3 = (int)r3;
        uint32_t packed = (uint32_t)(q0 & 0xFF) | ((uint32_t)(q1 & 0xFF) << 8) |
                          ((uint32_t)(q2 & 0xFF) << 16) | ((uint32_t)(q3 & 0xFF) << 24);
        reinterpret_cast<uint32_t*>(g_xq)[base + k * 256] = packed;
    }
}

// ============================================================================
// Kernel 2: transpose weight [K,M] -> [M,K] int8, with inline dtype detection
// (the harness promotes int8 tensors; each block samples 1024 words — L2-hot).
// ============================================================================
__global__ __launch_bounds__(256) void wtrans_kernel(const void* __restrict__ wsrc) {
    __shared__ int8_t t[32][33];
    __shared__ int s_mode;
    {
        const int32_t* wi = (const int32_t*)wsrc;
        const float*   wf = (const float*)wsrc;
        bool ok32 = true, okf = true;
        for (int i = threadIdx.x; i < 1024; i += 256) {
            int32_t a = wi[i];
            ok32 &= (a >= -128 && a <= 127);
            float f = wf[i];
            okf  &= (f == rintf(f) && f >= -128.f && f <= 127.f);
        }
        ok32 = __syncthreads_and(ok32);
        okf  = __syncthreads_and(okf);
        if (threadIdx.x == 0) s_mode = ok32 ? 1 : (okf ? 2 : 0);
        __syncthreads();
    }
    const int mode = s_mode;
    const int kb = blockIdx.x * 32, mb = blockIdx.y * 32;
    const int tx = threadIdx.x & 31, ty = threadIdx.x >> 5;
    const int8_t*  w8 = (const int8_t*)wsrc;
    const int32_t* wi = (const int32_t*)wsrc;
    const float*   wf = (const float*)wsrc;
#pragma unroll
    for (int i = 0; i < 4; ++i) {
        int r = ty + i * 8;
        size_t idx = (size_t)(kb + r) * MDIM + mb + tx;
        int8_t v;
        if (mode == 1)      v = (int8_t)wi[idx];
        else if (mode == 2) v = (int8_t)(int)wf[idx];
        else                v = w8[idx];
        t[r][tx] = v;
    }
    __syncthreads();
#pragma unroll
    for (int i = 0; i < 4; ++i) {
        int r = ty + i * 8;
        g_wb[(size_t)(mb + r) * KDIM + kb + tx] = t[tx][r];
    }
}

// ============================================================================
// Kernel 3: int8 GEMM. CTA: 128 tokens x 96 cols, 128 threads (4 warps, 2x2),
// warp tile 64x48 = 4x6 mma(16x8x32) frags. 5-stage cp.async, 1 sync/stage.
// ============================================================================
__global__ __launch_bounds__(128, 2)
void gemm_kernel(const float* __restrict__ bias, float* __restrict__ out) {
    extern __shared__ char smem[];
    const uint32_t sbase = smem_to_u32(smem);
    const int tid  = threadIdx.x;
    const int lane = tid & 31;
    const int warp = tid >> 5;
    const int wm = warp >> 1;          // 0..1 : token half (64 rows)
    const int wn = warp & 1;           // 0..1 : col half (48 cols)
    const int m0 = blockIdx.x * TN;    // output column tile (8)
    const int n0 = blockIdx.y * TM;    // token tile (256)

    // stage loader: A 512 + B 384 chunks of 16B = 896 / 128 thr = 7 each
    auto load_stage = [&](int s) {
        const int buf = s % STAGES;
        const uint32_t sa = sbase + buf * STAGE_BYTES;
        const uint32_t sb = sa + A_TILE_BYTES;
        const int k0 = s * TK;
#pragma unroll
        for (int it = 0; it < 7; ++it) {
            int g = tid + it * 128;          // 0..895
            if (g < 512) {
                int row = g >> 2, c = g & 3;
                cp_async16(sa + row * ROWPAD + c * 16,
                           g_xq + (size_t)(n0 + row) * KDIM + k0 + c * 16);
            } else {
                int h = g - 512;             // 0..383
                int row = h >> 2, c = h & 3;
                cp_async16(sb + row * ROWPAD + c * 16,
                           g_wb + (size_t)(m0 + row) * KDIM + k0 + c * 16);
            }
        }
    };

    int acc[4][6][4];
#pragma unroll
    for (int i = 0; i < 4; ++i)
#pragma unroll
        for (int j = 0; j < 6; ++j)
#pragma unroll
            for (int k = 0; k < 4; ++k) acc[i][j][k] = 0;

    load_stage(0); CP_COMMIT();
    load_stage(1); CP_COMMIT();
    load_stage(2); CP_COMMIT();
    load_stage(3); CP_COMMIT();

    const int a_row = (lane & 7) + ((lane >> 3) & 1) * 8;   // 0..15
    const int a_kb  = (lane >> 4) * 16;                     // 0 or 16
    const int b_row = lane & 7;
    const int b_kb  = ((lane >> 3) & 1) * 16;

    for (int s = 0; s < NSTAGE_ITERS; ++s) {
        CP_WAIT3();                 // stage s complete (<=3 groups pending)
        __syncthreads();            // also: buffer (s-1)%5 fully consumed by all
        if (s + 4 < NSTAGE_ITERS) load_stage(s + 4);
        CP_COMMIT();                // unconditional: fixed group accounting

        const int buf = s % STAGES;
        const uint32_t sa = sbase + buf * STAGE_BYTES;
        const uint32_t sb = sa + A_TILE_BYTES;
#pragma unroll
        for (int kk = 0; kk < 2; ++kk) {   // two k32 steps per 64B stage
            uint32_t afrag[4][4], bfrag[6][2];
            const uint32_t abase =
                sa + (uint32_t)(wm * 64 + a_row) * ROWPAD + kk * 32 + a_kb;
#pragma unroll
            for (int mf = 0; mf < 4; ++mf)
                ldmatrix_x4(afrag[mf], abase + (uint32_t)mf * 16 * ROWPAD);
            const uint32_t bbase =
                sb + (uint32_t)(wn * 48 + b_row) * ROWPAD + kk * 32 + b_kb;
#pragma unroll
            for (int nf = 0; nf < 6; ++nf)
                ldmatrix_x2(bfrag[nf], bbase + (uint32_t)nf * 8 * ROWPAD);
#pragma unroll
            for (int mf = 0; mf < 4; ++mf)
#pragma unroll
                for (int nf = 0; nf < 6; ++nf)
                    mma_s8(acc[mf][nf], afrag[mf], bfrag[nf]);
        }
    }

    // ---- epilogue: dequant + bias, float2 stores
    const float eff = (float)(0.02 * 0.01);
    float2 bv[6];
#pragma unroll
    for (int nf = 0; nf < 6; ++nf) {
        const int col = m0 + wn * 48 + nf * 8 + 2 * (lane & 3);
        bv[nf].x = __ldg(bias + col);
        bv[nf].y = __ldg(bias + col + 1);
    }
#pragma unroll
    for (int mf = 0; mf < 4; ++mf) {
        const int row_lo = n0 + wm * 64 + mf * 16 + (lane >> 2);
        float* p_lo = out + (size_t)row_lo * MDIM;
        float* p_hi = p_lo + 8 * MDIM;
#pragma unroll
        for (int nf = 0; nf < 6; ++nf) {
            const int col = m0 + wn * 48 + nf * 8 + 2 * (lane & 3);
            float2 lo, hi;
            lo.x = (float)acc[mf][nf][0] * eff + bv[nf].x;
            lo.y = (float)acc[mf][nf][1] * eff + bv[nf].y;
            hi.x = (float)acc[mf][nf][2] * eff + bv[nf].x;
            hi.y = (float)acc[mf][nf][3] * eff + bv[nf].y;
            *reinterpret_cast<float2*>(p_lo + col) = lo;
            *reinterpret_cast<float2*>(p_hi + col) = hi;
        }
    }
}

// ============================================================================
// Launch
// ============================================================================
extern "C" void kernel_launch(void* const* d_in, const int* in_sizes, int n_in,
                              void* d_out, int out_size) {
    const float* x    = (const float*)d_in[0];
    const void*  wt   = d_in[1];
    const float* bias = (const float*)d_in[2];
    float*       out  = (float*)d_out;

    cudaFuncSetAttribute(gemm_kernel, cudaFuncAttributeMaxDynamicSharedMemorySize,
                         SMEM_TOTAL);

    {
        int nblk = (N_TOK * KDIM) / 4 / 1024;   // 1536
        quant_kernel<<<nblk, 256>>>(x);
    }
    {
        dim3 grid(KDIM / 32, MDIM / 32);
        wtrans_kernel<<<grid, 256>>>(wt);
    }
    {
        dim3 grid(MDIM / TN, N_TOK / TM);   // (8, 256) = 2048 tiles
        gemm_kernel<<<grid, 128, SMEM_TOTAL>>>(bias, out);
    }
    (void)in_sizes; (void)n_in; (void)out_size;
}

// round 6
// speedup vs baseline: 1.0870x; 1.0870x over previous
#include <cuda_runtime.h>
#include <cuda_bf16.h>
#include <cstdint>

// ============================================================================
// x(8,4096,768) fp32 -> int8 quant -> GEMM vs weight_t(768,768) int8 (promoted
// to int32/fp32 by harness; detected) -> int32 acc * 2e-4 + bias -> fp32 out.
// Legacy mma.sync int8 path (compute_103 baseline PTX; tcgen05 unavailable).
// R6: TN=96 tiles (2048 -> 6.92 waves -> 98.8% wave eff) AND 256 thr/CTA
//     (8 warps -> 16 warps/SM = R3's proven tensor-saturation point).
//     Warp tile 32x48, acc regs 48/warp. B frags via ldmatrix.x4.
// ============================================================================
static constexpr int N_TOK = 32768;
static constexpr int KDIM  = 768;
static constexpr int MDIM  = 768;

static constexpr int TM = 128;      // token tile
static constexpr int TN = 96;       // out-col tile
static constexpr int TK = 64;       // K bytes per stage
static constexpr int STAGES = 5;
static constexpr int NSTAGE_ITERS = KDIM / TK;   // 12
static constexpr int ROWPAD = 80;   // 64B data padded to 80B: conflict-free ldmatrix
static constexpr int A_TILE_BYTES = TM * ROWPAD;        // 10240
static constexpr int B_TILE_BYTES = TN * ROWPAD;        // 7680
static constexpr int STAGE_BYTES  = A_TILE_BYTES + B_TILE_BYTES;  // 17920
static constexpr int SMEM_TOTAL   = STAGES * STAGE_BYTES;         // 89600 -> 2 CTA/SM

// Scratch (__device__ globals: the allowed allocation-free path)
__device__ int8_t g_xq[(size_t)N_TOK * KDIM];   // quantized activations [N,K]
__device__ int8_t g_wb[(size_t)MDIM * KDIM];    // weight transposed to [M,K]

// ============================================================================
// PTX helpers (baseline sm_75/sm_80 era, safe at compute_103)
// ============================================================================
__device__ __forceinline__ uint32_t smem_to_u32(const void* p) {
    uint32_t a;
    asm("{ .reg .u64 t; cvta.to.shared.u64 t, %1; cvt.u32.u64 %0, t; }" : "=r"(a) : "l"(p));
    return a;
}

__device__ __forceinline__ void cp_async16(uint32_t dst, const void* src) {
    asm volatile("cp.async.cg.shared.global [%0], [%1], 16;" :: "r"(dst), "l"(src));
}
#define CP_COMMIT() asm volatile("cp.async.commit_group;" ::: "memory")
#define CP_WAIT3()  asm volatile("cp.async.wait_group 3;" ::: "memory")

__device__ __forceinline__ void ldmatrix_x4(uint32_t* r, uint32_t addr) {
    asm volatile("ldmatrix.sync.aligned.m8n8.x4.shared.b16 {%0,%1,%2,%3}, [%4];"
                 : "=r"(r[0]), "=r"(r[1]), "=r"(r[2]), "=r"(r[3]) : "r"(addr));
}

__device__ __forceinline__ void mma_s8(int* c, const uint32_t* a, const uint32_t* b) {
    asm volatile(
        "mma.sync.aligned.m16n8k32.row.col.s32.s8.s8.s32 "
        "{%0,%1,%2,%3}, {%4,%5,%6,%7}, {%8,%9}, {%0,%1,%2,%3};"
        : "+r"(c[0]), "+r"(c[1]), "+r"(c[2]), "+r"(c[3])
        : "r"(a[0]), "r"(a[1]), "r"(a[2]), "r"(a[3]), "r"(b[0]), "r"(b[1]));
}

// ============================================================================
// Kernel 1: quantize x -> int8. q = clamp(round(x / 0.02f), -128, 127),
// IEEE fp32 division to mirror the reference. 8 float4 per thread (MLP=8).
// ============================================================================
__global__ __launch_bounds__(256) void quant_kernel(const float* __restrict__ x) {
    const int base = blockIdx.x * 2048 + threadIdx.x;   // float4 index
    const float4* xv = reinterpret_cast<const float4*>(x);
    float4 v[8];
#pragma unroll
    for (int k = 0; k < 8; ++k) v[k] = xv[base + k * 256];
#pragma unroll
    for (int k = 0; k < 8; ++k) {
        float r0 = fminf(fmaxf(rintf(__fdiv_rn(v[k].x, 0.02f)), -128.f), 127.f);
        float r1 = fminf(fmaxf(rintf(__fdiv_rn(v[k].y, 0.02f)), -128.f), 127.f);
        float r2 = fminf(fmaxf(rintf(__fdiv_rn(v[k].z, 0.02f)), -128.f), 127.f);
        float r3 = fminf(fmaxf(rintf(__fdiv_rn(v[k].w, 0.02f)), -128.f), 127.f);
        int q0 = (int)r0, q1 = (int)r1, q2 = (int)r2, q3 = (int)r3;
        uint32_t packed = (uint32_t)(q0 & 0xFF) | ((uint32_t)(q1 & 0xFF) << 8) |
                          ((uint32_t)(q2 & 0xFF) << 16) | ((uint32_t)(q3 & 0xFF) << 24);
        reinterpret_cast<uint32_t*>(g_xq)[base + k * 256] = packed;
    }
}

// ============================================================================
// Kernel 2: transpose weight [K,M] -> [M,K] int8, with inline dtype detection
// (the harness promotes int8 tensors; each block samples 1024 words — L2-hot).
// ============================================================================
__global__ __launch_bounds__(256) void wtrans_kernel(const void* __restrict__ wsrc) {
    __shared__ int8_t t[32][33];
    __shared__ int s_mode;
    {
        const int32_t* wi = (const int32_t*)wsrc;
        const float*   wf = (const float*)wsrc;
        bool ok32 = true, okf = true;
        for (int i = threadIdx.x; i < 1024; i += 256) {
            int32_t a = wi[i];
            ok32 &= (a >= -128 && a <= 127);
            float f = wf[i];
            okf  &= (f == rintf(f) && f >= -128.f && f <= 127.f);
        }
        ok32 = __syncthreads_and(ok32);
        okf  = __syncthreads_and(okf);
        if (threadIdx.x == 0) s_mode = ok32 ? 1 : (okf ? 2 : 0);
        __syncthreads();
    }
    const int mode = s_mode;
    const int kb = blockIdx.x * 32, mb = blockIdx.y * 32;
    const int tx = threadIdx.x & 31, ty = threadIdx.x >> 5;
    const int8_t*  w8 = (const int8_t*)wsrc;
    const int32_t* wi = (const int32_t*)wsrc;
    const float*   wf = (const float*)wsrc;
#pragma unroll
    for (int i = 0; i < 4; ++i) {
        int r = ty + i * 8;
        size_t idx = (size_t)(kb + r) * MDIM + mb + tx;
        int8_t v;
        if (mode == 1)      v = (int8_t)wi[idx];
        else if (mode == 2) v = (int8_t)(int)wf[idx];
        else                v = w8[idx];
        t[r][tx] = v;
    }
    __syncthreads();
#pragma unroll
    for (int i = 0; i < 4; ++i) {
        int r = ty + i * 8;
        g_wb[(size_t)(mb + r) * KDIM + kb + tx] = t[tx][r];
    }
}

// ============================================================================
// Kernel 3: int8 GEMM. CTA: 128 tokens x 96 cols, 256 threads (8 warps, 4x2),
// warp tile 32x48 = 2x6 mma(16x8x32) frags. 5-stage cp.async, 1 sync/stage.
// ============================================================================
__global__ __launch_bounds__(256, 2)
void gemm_kernel(const float* __restrict__ bias, float* __restrict__ out) {
    extern __shared__ char smem[];
    const uint32_t sbase = smem_to_u32(smem);
    const int tid  = threadIdx.x;
    const int lane = tid & 31;
    const int warp = tid >> 5;
    const int wm = warp >> 1;          // 0..3 : 32-token slab
    const int wn = warp & 1;           // 0..1 : 48-col slab
    const int m0 = blockIdx.x * TN;    // output column tile (8)
    const int n0 = blockIdx.y * TM;    // token tile (256)

    // stage loader: A 512 + B 384 chunks of 16B = 896; 256 thr -> 4 iters (last partial)
    auto load_stage = [&](int s) {
        const int buf = s % STAGES;
        const uint32_t sa = sbase + buf * STAGE_BYTES;
        const uint32_t sb = sa + A_TILE_BYTES;
        const int k0 = s * TK;
#pragma unroll
        for (int it = 0; it < 4; ++it) {
            int g = tid + it * 256;          // 0..1023; active < 896
            if (g < 512) {
                int row = g >> 2, c = g & 3;
                cp_async16(sa + row * ROWPAD + c * 16,
                           g_xq + (size_t)(n0 + row) * KDIM + k0 + c * 16);
            } else if (g < 896) {
                int h = g - 512;             // 0..383
                int row = h >> 2, c = h & 3;
                cp_async16(sb + row * ROWPAD + c * 16,
                           g_wb + (size_t)(m0 + row) * KDIM + k0 + c * 16);
            }
        }
    };

    int acc[2][6][4];
#pragma unroll
    for (int i = 0; i < 2; ++i)
#pragma unroll
        for (int j = 0; j < 6; ++j)
#pragma unroll
            for (int k = 0; k < 4; ++k) acc[i][j][k] = 0;

    load_stage(0); CP_COMMIT();
    load_stage(1); CP_COMMIT();
    load_stage(2); CP_COMMIT();
    load_stage(3); CP_COMMIT();

    // A ldmatrix.x4 lane mapping (m16 x k32): row 0..15, k-half 0/16
    const int a_row = (lane & 7) + ((lane >> 3) & 1) * 8;
    const int a_kb  = (lane >> 4) * 16;
    // B ldmatrix.x4 lane mapping (two 8-col groups x two k-halves)
    const int b_row = lane & 7;
    const int b_grp = (lane >> 4) & 1;      // second 8-col group
    const int b_kb  = ((lane >> 3) & 1) * 16;

    for (int s = 0; s < NSTAGE_ITERS; ++s) {
        CP_WAIT3();
        __syncthreads();
        if (s + 4 < NSTAGE_ITERS) load_stage(s + 4);
        CP_COMMIT();

        const int buf = s % STAGES;
        const uint32_t sa = sbase + buf * STAGE_BYTES;
        const uint32_t sb = sa + A_TILE_BYTES;
#pragma unroll
        for (int kk = 0; kk < 2; ++kk) {   // two k32 steps per 64B stage
            uint32_t afrag[2][4], bfrag[6][2];
            const uint32_t abase =
                sa + (uint32_t)(wm * 32 + a_row) * ROWPAD + kk * 32 + a_kb;
#pragma unroll
            for (int mf = 0; mf < 2; ++mf)
                ldmatrix_x4(afrag[mf], abase + (uint32_t)mf * 16 * ROWPAD);
            // B: 3 x ldmatrix.x4, each covers 16 cols x k32
            const uint32_t bbase =
                sb + (uint32_t)(wn * 48 + b_grp * 8 + b_row) * ROWPAD + kk * 32 + b_kb;
#pragma unroll
            for (int np = 0; np < 3; ++np) {
                uint32_t r[4];
                ldmatrix_x4(r, bbase + (uint32_t)np * 16 * ROWPAD);
                bfrag[np * 2 + 0][0] = r[0];
                bfrag[np * 2 + 0][1] = r[1];
                bfrag[np * 2 + 1][0] = r[2];
                bfrag[np * 2 + 1][1] = r[3];
            }
#pragma unroll
            for (int mf = 0; mf < 2; ++mf)
#pragma unroll
                for (int nf = 0; nf < 6; ++nf)
                    mma_s8(acc[mf][nf], afrag[mf], bfrag[nf]);
        }
    }

    // ---- epilogue: dequant + bias, float2 stores
    const float eff = (float)(0.02 * 0.01);
    float2 bv[6];
#pragma unroll
    for (int nf = 0; nf < 6; ++nf) {
        const int col = m0 + wn * 48 + nf * 8 + 2 * (lane & 3);
        bv[nf].x = __ldg(bias + col);
        bv[nf].y = __ldg(bias + col + 1);
    }
#pragma unroll
    for (int mf = 0; mf < 2; ++mf) {
        const int row_lo = n0 + wm * 32 + mf * 16 + (lane >> 2);
        float* p_lo = out + (size_t)row_lo * MDIM;
        float* p_hi = p_lo + 8 * MDIM;
#pragma unroll
        for (int nf = 0; nf < 6; ++nf) {
            const int col = m0 + wn * 48 + nf * 8 + 2 * (lane & 3);
            float2 lo, hi;
            lo.x = (float)acc[mf][nf][0] * eff + bv[nf].x;
            lo.y = (float)acc[mf][nf][1] * eff + bv[nf].y;
            hi.x = (float)acc[mf][nf][2] * eff + bv[nf].x;
            hi.y = (float)acc[mf][nf][3] * eff + bv[nf].y;
            *reinterpret_cast<float2*>(p_lo + col) = lo;
            *reinterpret_cast<float2*>(p_hi + col) = hi;
        }
    }
}

// ============================================================================
// Launch
// ============================================================================
extern "C" void kernel_launch(void* const* d_in, const int* in_sizes, int n_in,
                              void* d_out, int out_size) {
    const float* x    = (const float*)d_in[0];
    const void*  wt   = d_in[1];
    const float* bias = (const float*)d_in[2];
    float*       out  = (float*)d_out;

    cudaFuncSetAttribute(gemm_kernel, cudaFuncAttributeMaxDynamicSharedMemorySize,
                         SMEM_TOTAL);

    {
        int nblk = (N_TOK * KDIM) / 4 / 2048;   // 3072 float4 per block -> 3072 blocks? no: 768
        quant_kernel<<<nblk, 256>>>(x);
    }
    {
        dim3 grid(KDIM / 32, MDIM / 32);
        wtrans_kernel<<<grid, 256>>>(wt);
    }
    {
        dim3 grid(MDIM / TN, N_TOK / TM);   // (8, 256) = 2048 tiles
        gemm_kernel<<<grid, 256, SMEM_TOTAL>>>(bias, out);
    }
    (void)in_sizes; (void)n_in; (void)out_size;
}